// round 14
// baseline (speedup 1.0000x reference)
#include <cuda_runtime.h>
#include <math.h>

#define BB    2
#define HH    360
#define WG    360
#define HW    (HH*WG)          // 129600
#define NCLS  10
#define NPROP 200
#define CC    128
#define NPTS  80000
#define NBUCK 65536            // bucket = float_bits >> 16
#define SEL_CAP 4096

// output layout: qf (B,C,P) | query_pos (B,P,2) | qhs (B,NCLS,P) | cls (B,P)
#define OFF_QF  0
#define OFF_POS (BB*CC*NPROP)            // 51200
#define OFF_QHS (OFF_POS + BB*NPROP*2)   // 52000
#define OFF_CLS (OFF_QHS + BB*NCLS*NPROP)// 56000

typedef unsigned long long ull;

// ---------------- scratch (device globals; re-initialized every launch) ----
__device__ float g_heat[BB*NCLS*HW];     // raw sigmoid heat, dense planar
__device__ float g_supp[BB*NCLS*HW];     // suppressed heat, dense planar
__device__ int   g_map [BB*HW];          // cell -> point row (-1 empty)
__device__ unsigned g_hist[BB*NBUCK];
__device__ int   g_thr[BB];
__device__ int   g_selcnt[BB];
__device__ ull   g_sel[BB*SEL_CAP];
__device__ ull   g_top[BB*NPROP];

// ---------------- packed f32x2 helpers --------------------------------------
__device__ __forceinline__ ull pk2(float lo, float hi) {
    ull r;
    asm("mov.b64 %0, {%1, %2};" : "=l"(r)
        : "r"(__float_as_uint(lo)), "r"(__float_as_uint(hi)));
    return r;
}
__device__ __forceinline__ ull pk1(float v) {
    ull r;
    asm("mov.b64 %0, {%1, %1};" : "=l"(r) : "r"(__float_as_uint(v)));
    return r;
}
__device__ __forceinline__ void upk(ull p, float& lo, float& hi) {
    unsigned a, b;
    asm("mov.b64 {%0, %1}, %2;" : "=r"(a), "=r"(b) : "l"(p));
    lo = __uint_as_float(a); hi = __uint_as_float(b);
}
__device__ __forceinline__ ull ffma2(ull a, ull b, ull c) {
    ull d;
    asm("fma.rn.f32x2 %0, %1, %2, %3;" : "=l"(d) : "l"(a), "l"(b), "l"(c));
    return d;
}

// ---------------- init (3 kernels: puts gemm at launch index 3) -------------
__global__ void initA_kernel() {      // zero g_heat
    int stride = gridDim.x * blockDim.x;
    int i0 = blockIdx.x * blockDim.x + threadIdx.x;
    float4 z4 = make_float4(0.f, 0.f, 0.f, 0.f);
    for (int j = i0; j < BB*NCLS*HW/4; j += stride) ((float4*)g_heat)[j] = z4;
}
__global__ void initB_kernel() {      // zero g_supp
    int stride = gridDim.x * blockDim.x;
    int i0 = blockIdx.x * blockDim.x + threadIdx.x;
    float4 z4 = make_float4(0.f, 0.f, 0.f, 0.f);
    for (int j = i0; j < BB*NCLS*HW/4; j += stride) ((float4*)g_supp)[j] = z4;
}
__global__ void initC_kernel() {      // map=-1, hist=0, counters=0
    int stride = gridDim.x * blockDim.x;
    int i0 = blockIdx.x * blockDim.x + threadIdx.x;
    int4 m4 = make_int4(-1, -1, -1, -1);
    for (int j = i0; j < BB*HW/4; j += stride) ((int4*)g_map)[j] = m4;
    uint4 zu = make_uint4(0u, 0u, 0u, 0u);
    for (int j = i0; j < BB*NBUCK/4; j += stride) ((uint4*)g_hist)[j] = zu;
    if (i0 < BB) g_selcnt[i0] = 0;
}

// ---------------- fused MLP head: 512 threads, 4x8 micro-tile, dup-A --------
// block: 512 threads, 128x128 tile. W1 resident in smem (natural layout);
// A staged as duplicated f32x2 pairs (no pk1 in inner loop).
// smem(floats): sW1 [0,16384) | sA2(ull,32x130) [16384,24704) |
//               sH reuse [0,16896) | sW2 [24704,25984)
#define SMEM_FLOATS 25984
__global__ void __launch_bounds__(512, 2)
gemm_kernel(const float* __restrict__ feat, const float* __restrict__ W1,
            const float* __restrict__ b1,  const float* __restrict__ W2,
            const float* __restrict__ b2,  const int* __restrict__ idxs)
{
    extern __shared__ float sm[];
    float* sW1 = sm;                        // 128*128
    ull*   sA2 = (ull*)(sm + 16384);        // 32 x 130 dup pairs
    float* sH  = sm;                        // 128*132 (reuses W1 + head of A)
    float* sW2 = sm + 24704;                // 128*10

    const int tid = threadIdx.x;
    const int rowBase = blockIdx.x * 128;

    for (int i = tid*4; i < CC*CC; i += 512*4)
        *(float4*)(sW1 + i) = *(const float4*)(W1 + i);
    for (int i = tid; i < CC*NCLS; i += 512)
        sW2[i] = W2[i];

    const int tn = tid & 15;          // 0..15 : column group
    const int tm = tid >> 4;          // 0..31 : 4-row group
    const int c0 = tn*4;              // cols c0..c0+3
    const int c1 = 64 + tn*4;         // cols c1..c1+3

    // acc pairs: [i][0]=(c0,c0+1) [i][1]=(c0+2,c0+3) [i][2]=(c1,c1+1) [i][3]=(c1+2,c1+3)
    ull acc2[4][4];
    {
        ull p0 = pk2(b1[c0],   b1[c0+1]);
        ull p1 = pk2(b1[c0+2], b1[c0+3]);
        ull p2 = pk2(b1[c1],   b1[c1+1]);
        ull p3 = pk2(b1[c1+2], b1[c1+3]);
#pragma unroll
        for (int i = 0; i < 4; i++) {
            acc2[i][0] = p0; acc2[i][1] = p1; acc2[i][2] = p2; acc2[i][3] = p3;
        }
    }
    __syncthreads();   // W1/W2 visible

    const int lrow = tid >> 2;          // 0..127 (A-load row)
    const int lk8  = (tid & 3) * 8;     // 0,8,16,24 (A-load k octet)
    for (int kc = 0; kc < 4; kc++) {
        {
            const float* fp = feat + (size_t)(rowBase + lrow)*CC + kc*32 + lk8;
            float4 v0 = *(const float4*)(fp);
            float4 v1 = *(const float4*)(fp + 4);
            sA2[(lk8+0)*130 + lrow] = pk1(v0.x);
            sA2[(lk8+1)*130 + lrow] = pk1(v0.y);
            sA2[(lk8+2)*130 + lrow] = pk1(v0.z);
            sA2[(lk8+3)*130 + lrow] = pk1(v0.w);
            sA2[(lk8+4)*130 + lrow] = pk1(v1.x);
            sA2[(lk8+5)*130 + lrow] = pk1(v1.y);
            sA2[(lk8+6)*130 + lrow] = pk1(v1.z);
            sA2[(lk8+7)*130 + lrow] = pk1(v1.w);
        }
        __syncthreads();
#pragma unroll 4
        for (int k = 0; k < 32; k++) {
            const ull* ap = sA2 + k*130 + tm*4;
            ulonglong2 A01 = *(const ulonglong2*)(ap);       // rows tm*4, tm*4+1
            ulonglong2 A23 = *(const ulonglong2*)(ap + 2);   // rows tm*4+2, tm*4+3
            const ull* bw = (const ull*)(sW1 + (kc*32+k)*CC);
            ulonglong2 W01 = *(const ulonglong2*)(bw + tn*2);       // cols c0..c0+3
            ulonglong2 W23 = *(const ulonglong2*)(bw + 32 + tn*2);  // cols c1..c1+3
            acc2[0][0]=ffma2(A01.x,W01.x,acc2[0][0]); acc2[0][1]=ffma2(A01.x,W01.y,acc2[0][1]);
            acc2[0][2]=ffma2(A01.x,W23.x,acc2[0][2]); acc2[0][3]=ffma2(A01.x,W23.y,acc2[0][3]);
            acc2[1][0]=ffma2(A01.y,W01.x,acc2[1][0]); acc2[1][1]=ffma2(A01.y,W01.y,acc2[1][1]);
            acc2[1][2]=ffma2(A01.y,W23.x,acc2[1][2]); acc2[1][3]=ffma2(A01.y,W23.y,acc2[1][3]);
            acc2[2][0]=ffma2(A23.x,W01.x,acc2[2][0]); acc2[2][1]=ffma2(A23.x,W01.y,acc2[2][1]);
            acc2[2][2]=ffma2(A23.x,W23.x,acc2[2][2]); acc2[2][3]=ffma2(A23.x,W23.y,acc2[2][3]);
            acc2[3][0]=ffma2(A23.y,W01.x,acc2[3][0]); acc2[3][1]=ffma2(A23.y,W01.y,acc2[3][1]);
            acc2[3][2]=ffma2(A23.y,W23.x,acc2[3][2]); acc2[3][3]=ffma2(A23.y,W23.y,acc2[3][3]);
        }
        __syncthreads();
    }

    // relu -> sH (packed 8B stores)
#pragma unroll
    for (int i = 0; i < 4; i++) {
        int r = tm*4 + i;
        float lo, hi;
        upk(acc2[i][0], lo, hi);
        *(ull*)(sH + r*132 + c0)     = pk2(fmaxf(lo,0.f), fmaxf(hi,0.f));
        upk(acc2[i][1], lo, hi);
        *(ull*)(sH + r*132 + c0 + 2) = pk2(fmaxf(lo,0.f), fmaxf(hi,0.f));
        upk(acc2[i][2], lo, hi);
        *(ull*)(sH + r*132 + c1)     = pk2(fmaxf(lo,0.f), fmaxf(hi,0.f));
        upk(acc2[i][3], lo, hi);
        *(ull*)(sH + r*132 + c1 + 2) = pk2(fmaxf(lo,0.f), fmaxf(hi,0.f));
    }
    __syncthreads();

    // phase 2: hm = H @ W2 + b2, sigmoid, scatter (threads 0..255)
    if (tid < 256) {
        const int r   = tid & 127;
        const int grp = tid >> 7;      // 0 -> cls 0..4, 1 -> cls 5..9
        float o[5];
#pragma unroll
        for (int i = 0; i < 5; i++) o[i] = b2[grp*5 + i];
        for (int j = 0; j < 128; j++) {
            float a = sH[r*132 + j];
#pragma unroll
            for (int i = 0; i < 5; i++)
                o[i] = fmaf(a, sW2[j*NCLS + grp*5 + i], o[i]);
        }
        const int gr = rowBase + r;
        const int bi = idxs[gr*3], yi = idxs[gr*3+1], xi = idxs[gr*3+2];
        const int cell = yi*WG + xi;
#pragma unroll
        for (int i = 0; i < 5; i++) {
            int c = grp*5 + i;
            float heat = 1.f / (1.f + expf(-o[i]));
            g_heat[(bi*NCLS + c)*HW + cell] = heat;
        }
        if (grp == 0) g_map[bi*HW + cell] = gr;
    }
}

// ---------------- NMS + histogram -------------------------------------------
__global__ void nms_kernel() {
    int gid = blockIdx.x * blockDim.x + threadIdx.x;   // over B*HW
    if (gid >= BB*HW) return;
    if (g_map[gid] < 0) return;                        // empty cell: supp stays 0
    int b = gid / HW, cell = gid - b*HW;
    int y = cell / WG, x = cell - y*WG;
    bool inner = (y > 0) & (y < HH-1) & (x > 0) & (x < WG-1);
    const float* hb = g_heat + (size_t)b*NCLS*HW;
    for (int c = 0; c < NCLS; c++) {
        const float* hc = hb + c*HW;
        float ctr = hc[cell];
        float s;
        if (c >= 8) {
            s = ctr;
        } else if (!inner) {
            s = 0.f;   // border: local_max==0, heat>0 -> suppressed
        } else {
            bool keep = (ctr >= hc[cell-WG-1]) & (ctr >= hc[cell-WG]) & (ctr >= hc[cell-WG+1])
                      & (ctr >= hc[cell-1])                           & (ctr >= hc[cell+1])
                      & (ctr >= hc[cell+WG-1]) & (ctr >= hc[cell+WG]) & (ctr >= hc[cell+WG+1]);
            s = keep ? ctr : 0.f;
        }
        if (s > 0.f) {
            g_supp[((size_t)b*NCLS + c)*HW + cell] = s;
            atomicAdd(&g_hist[b*NBUCK + (__float_as_uint(s) >> 16)], 1u);
        }
    }
}

// ---------------- threshold bucket of rank-200 (warp-shuffle suffix scan) ---
__global__ void thresh_kernel() {
    __shared__ unsigned wtot[32], wexc[32];
    int b = blockIdx.x;
    const unsigned* h = g_hist + b*NBUCK;
    int t = threadIdx.x;                 // 1024 threads x 64 buckets
    const uint4* hv4 = (const uint4*)(h + t*64);
    unsigned v = 0;
#pragma unroll
    for (int i = 0; i < 16; i++) {
        uint4 u = hv4[i];
        v += u.x + u.y + u.z + u.w;
    }
    int lane = t & 31, wid = t >> 5;
    unsigned s = v;                      // inclusive lane-suffix within warp
#pragma unroll
    for (int off = 1; off < 32; off <<= 1) {
        unsigned u = __shfl_down_sync(0xFFFFFFFFu, s, off);
        if (lane + off < 32) s += u;
    }
    if (lane == 0) wtot[wid] = s;
    __syncthreads();
    if (wid == 0) {
        unsigned ws = wtot[lane];
        unsigned sw = ws;
#pragma unroll
        for (int off = 1; off < 32; off <<= 1) {
            unsigned u = __shfl_down_sync(0xFFFFFFFFu, sw, off);
            if (lane + off < 32) sw += u;
        }
        wexc[lane] = sw - ws;            // strict suffix of warp totals
    }
    __syncthreads();
    unsigned S = s + wexc[wid];          // suffix over all t' >= t
    unsigned Snext = S - v;
    if (S >= NPROP && Snext < NPROP) {   // exactly one thread
        unsigned acc = Snext;
        int T = t*64;
        for (int i = 63; i >= 0; i--) {
            unsigned c = h[t*64 + i];    // L1 hot
            if (acc + c >= NPROP) { T = t*64 + i; break; }
            acc += c;
        }
        g_thr[b] = T;
    }
}

// ---------------- gather candidates >= threshold from DENSE supp ------------
__global__ void gather_kernel() {
    const int N4 = BB*NCLS*HW/4;
    int gid = blockIdx.x * blockDim.x + threadIdx.x;
    if (gid >= N4) return;
    float4 v = ((const float4*)g_supp)[gid];
    int base = gid * 4;
    int b = base / (NCLS*HW);
    int T = g_thr[b];
    float vv[4] = {v.x, v.y, v.z, v.w};
#pragma unroll
    for (int u = 0; u < 4; u++) {
        unsigned vb = __float_as_uint(vv[u]);
        if ((int)(vb >> 16) >= T) {
            unsigned j = (unsigned)(base + u - b*NCLS*HW);   // key = c*HW + cell
            ull sk = ((ull)vb << 32) | (ull)(0xFFFFFFFFu - j);
            int p = atomicAdd(&g_selcnt[b], 1);
            if (p < SEL_CAP) g_sel[b*SEL_CAP + p] = sk;
        }
    }
}

// ---------------- exact rank of the small selected set ----------------------
__global__ void rank_kernel() {
    __shared__ ull sk[SEL_CAP];
    int b = blockIdx.x;
    int M = g_selcnt[b]; if (M > SEL_CAP) M = SEL_CAP;
    for (int i = threadIdx.x; i < M; i += blockDim.x) sk[i] = g_sel[b*SEL_CAP + i];
    __syncthreads();
    for (int i = threadIdx.x; i < M; i += blockDim.x) {
        ull v = sk[i];
        int r = 0;
        for (int j = 0; j < M; j++) r += (sk[j] > v);
        if (r < NPROP) g_top[b*NPROP + r] = v;
    }
}

// ---------------- assemble outputs ------------------------------------------
__global__ void out_kernel(const float* __restrict__ feat,
                           const float* __restrict__ Wcls,
                           const float* __restrict__ bcls,
                           float* __restrict__ out)
{
    int b = blockIdx.x / NPROP, p = blockIdx.x - b*NPROP;
    ull sk = g_top[b*NPROP + p];
    unsigned key = 0xFFFFFFFFu - (unsigned)(sk & 0xFFFFFFFFu);
    int cls = key / HW, idx = key - cls*HW;
    int c = threadIdx.x;
    int row = g_map[b*HW + idx];
    float f = (row >= 0) ? feat[(size_t)row*CC + c] : 0.f;
    out[OFF_QF + (b*CC + c)*NPROP + p] = f + Wcls[c*NCLS + cls] + bcls[c];
    if (c < NCLS)
        out[OFF_QHS + (b*NCLS + c)*NPROP + p] = g_supp[((size_t)b*NCLS + c)*HW + idx];
    if (c == 0) {
        out[OFF_POS + (b*NPROP + p)*2 + 0] = (float)(idx % WG);
        out[OFF_POS + (b*NPROP + p)*2 + 1] = (float)(idx / WG);
        out[OFF_CLS + b*NPROP + p] = (float)cls;
    }
}

// ---------------- launch ----------------------------------------------------
extern "C" void kernel_launch(void* const* d_in, const int* in_sizes, int n_in,
                              void* d_out, int out_size)
{
    const float* feat = (const float*)d_in[0];
    const float* W1   = (const float*)d_in[1];
    const float* b1   = (const float*)d_in[2];
    const float* W2   = (const float*)d_in[3];
    const float* b2   = (const float*)d_in[4];
    const float* Wcls = (const float*)d_in[5];
    const float* bcls = (const float*)d_in[6];
    const int*   idxs = (const int*)d_in[7];
    float* out = (float*)d_out;

    cudaFuncSetAttribute(gemm_kernel, cudaFuncAttributeMaxDynamicSharedMemorySize,
                         SMEM_FLOATS * (int)sizeof(float));

    // launch index 3 == gemm  (profiler captures index 3)
    initA_kernel<<<1024, 256>>>();
    initB_kernel<<<1024, 256>>>();
    initC_kernel<<<512, 256>>>();
    gemm_kernel<<<NPTS/128, 512, SMEM_FLOATS * sizeof(float)>>>(feat, W1, b1, W2, b2, idxs);
    nms_kernel<<<(BB*HW + 255)/256, 256>>>();
    thresh_kernel<<<BB, 1024>>>();
    gather_kernel<<<(BB*NCLS*HW/4 + 255)/256, 256>>>();
    rank_kernel<<<BB, 1024>>>();
    out_kernel<<<BB*NPROP, CC>>>(feat, Wcls, bcls, out);
}

// round 15
// speedup vs baseline: 1.1569x; 1.1569x over previous
#include <cuda_runtime.h>
#include <math.h>

#define BB    2
#define HH    360
#define WG    360
#define HW    (HH*WG)          // 129600
#define NCLS  10
#define NPROP 200
#define CC    128
#define NPTS  80000
#define NBUCK 65536            // bucket = float_bits >> 16
#define SEL_CAP 4096

// output layout: qf (B,C,P) | query_pos (B,P,2) | qhs (B,NCLS,P) | cls (B,P)
#define OFF_QF  0
#define OFF_POS (BB*CC*NPROP)            // 51200
#define OFF_QHS (OFF_POS + BB*NPROP*2)   // 52000
#define OFF_CLS (OFF_QHS + BB*NCLS*NPROP)// 56000

typedef unsigned long long ull;

// ---------------- scratch (device globals; re-initialized every launch) ----
__device__ float g_heat[BB*NCLS*HW];     // raw sigmoid heat, dense planar
__device__ float g_supp[BB*NCLS*HW];     // suppressed heat, dense planar
__device__ int   g_map [BB*HW];          // cell -> point row (-1 empty)
__device__ unsigned g_hist[BB*NBUCK];
__device__ int   g_thr[BB];
__device__ int   g_selcnt[BB];
__device__ ull   g_sel[BB*SEL_CAP];
__device__ ull   g_top[BB*NPROP];

// ---------------- packed f32x2 helpers --------------------------------------
__device__ __forceinline__ ull pk2(float lo, float hi) {
    ull r;
    asm("mov.b64 %0, {%1, %2};" : "=l"(r)
        : "r"(__float_as_uint(lo)), "r"(__float_as_uint(hi)));
    return r;
}
__device__ __forceinline__ ull pk1(float v) {
    ull r;
    asm("mov.b64 %0, {%1, %1};" : "=l"(r) : "r"(__float_as_uint(v)));
    return r;
}
__device__ __forceinline__ void upk(ull p, float& lo, float& hi) {
    unsigned a, b;
    asm("mov.b64 {%0, %1}, %2;" : "=r"(a), "=r"(b) : "l"(p));
    lo = __uint_as_float(a); hi = __uint_as_float(b);
}
__device__ __forceinline__ ull ffma2(ull a, ull b, ull c) {
    ull d;
    asm("fma.rn.f32x2 %0, %1, %2, %3;" : "=l"(d) : "l"(a), "l"(b), "l"(c));
    return d;
}

// ---------------- init (3 kernels: puts gemm at launch index 3) -------------
__global__ void initA_kernel() {      // zero g_heat
    int stride = gridDim.x * blockDim.x;
    int i0 = blockIdx.x * blockDim.x + threadIdx.x;
    float4 z4 = make_float4(0.f, 0.f, 0.f, 0.f);
    for (int j = i0; j < BB*NCLS*HW/4; j += stride) ((float4*)g_heat)[j] = z4;
}
__global__ void initB_kernel() {      // zero g_supp
    int stride = gridDim.x * blockDim.x;
    int i0 = blockIdx.x * blockDim.x + threadIdx.x;
    float4 z4 = make_float4(0.f, 0.f, 0.f, 0.f);
    for (int j = i0; j < BB*NCLS*HW/4; j += stride) ((float4*)g_supp)[j] = z4;
}
__global__ void initC_kernel() {      // map=-1, hist=0, counters=0
    int stride = gridDim.x * blockDim.x;
    int i0 = blockIdx.x * blockDim.x + threadIdx.x;
    int4 m4 = make_int4(-1, -1, -1, -1);
    for (int j = i0; j < BB*HW/4; j += stride) ((int4*)g_map)[j] = m4;
    uint4 zu = make_uint4(0u, 0u, 0u, 0u);
    for (int j = i0; j < BB*NBUCK/4; j += stride) ((uint4*)g_hist)[j] = zu;
    if (i0 < BB) g_selcnt[i0] = 0;
}

// ---------------- fused MLP head: 64-row tiles, 4x8 micro, 3 blocks/SM ------
// block: 256 threads, 64 rows x 128 cols tile; W1 resident in smem.
// smem(floats): sW1 [0,16384) | sA(32k x 68) [16384,18560) |
//               sH reuse [0,8448) | sW2 overlays sA after mainloop
#define SMEM_FLOATS 18560
__global__ void __launch_bounds__(256, 3)
gemm_kernel(const float* __restrict__ feat, const float* __restrict__ W1,
            const float* __restrict__ b1,  const float* __restrict__ W2,
            const float* __restrict__ b2,  const int* __restrict__ idxs)
{
    extern __shared__ float sm[];
    float* sW1 = sm;                 // 128*128
    float* sA  = sm + 16384;         // 32 k x 68 (stride 68: aligned + low-conflict)
    float* sH  = sm;                 // 64*132 (reuses sW1 after mainloop)
    float* sW2 = sm + 16384;         // 128*10 (overlays sA after mainloop)

    const int tid = threadIdx.x;
    const int rowBase = blockIdx.x * 64;

    for (int i = tid*4; i < CC*CC; i += 256*4)
        *(float4*)(sW1 + i) = *(const float4*)(W1 + i);

    const int tn = tid & 15, tm = tid >> 4;   // tm 0..15 -> rows tm*4..tm*4+3
    const int c0 = tn*4;          // cols c0..c0+3
    const int c1 = 64 + tn*4;     // cols c1..c1+3

    // acc pairs: [i][0]=(c0,c0+1) [i][1]=(c0+2,c0+3) [i][2]=(c1,c1+1) [i][3]=(c1+2,c1+3)
    ull acc2[4][4];
    {
        ull p0 = pk2(b1[c0],   b1[c0+1]);
        ull p1 = pk2(b1[c0+2], b1[c0+3]);
        ull p2 = pk2(b1[c1],   b1[c1+1]);
        ull p3 = pk2(b1[c1+2], b1[c1+3]);
#pragma unroll
        for (int i = 0; i < 4; i++) {
            acc2[i][0] = p0; acc2[i][1] = p1; acc2[i][2] = p2; acc2[i][3] = p3;
        }
    }
    __syncthreads();   // W1 visible

    const int lrow = tid >> 3;          // 0..31
    const int lk4  = (tid & 7) * 4;     // 0..28
    for (int kc = 0; kc < 4; kc++) {
#pragma unroll
        for (int pass = 0; pass < 2; pass++) {
            int r = lrow + pass*32;
            float4 v = *(const float4*)(feat + (size_t)(rowBase + r)*CC + kc*32 + lk4);
            sA[(lk4+0)*68 + r] = v.x;
            sA[(lk4+1)*68 + r] = v.y;
            sA[(lk4+2)*68 + r] = v.z;
            sA[(lk4+3)*68 + r] = v.w;
        }
        __syncthreads();
#pragma unroll 4
        for (int k = 0; k < 32; k++) {
            float a[4];
            *(float4*)(a) = *(float4*)(sA + k*68 + tm*4);   // aligned: k*68, tm*4 both %4==0
            const ull* bw = (const ull*)(sW1 + (kc*32+k)*128);
            ull w0 = bw[tn*2];
            ull w1 = bw[tn*2 + 1];
            ull w2 = bw[32 + tn*2];
            ull w3 = bw[32 + tn*2 + 1];
#pragma unroll
            for (int i = 0; i < 4; i++) {
                ull aa = pk1(a[i]);
                acc2[i][0] = ffma2(aa, w0, acc2[i][0]);
                acc2[i][1] = ffma2(aa, w1, acc2[i][1]);
                acc2[i][2] = ffma2(aa, w2, acc2[i][2]);
                acc2[i][3] = ffma2(aa, w3, acc2[i][3]);
            }
        }
        __syncthreads();
    }

    // relu -> sH (overlays sW1; mainloop done) + load W2 into sA overlay
#pragma unroll
    for (int i = 0; i < 4; i++) {
        int r = tm*4 + i;
        float lo, hi;
        upk(acc2[i][0], lo, hi);
        *(ull*)(sH + r*132 + c0)     = pk2(fmaxf(lo,0.f), fmaxf(hi,0.f));
        upk(acc2[i][1], lo, hi);
        *(ull*)(sH + r*132 + c0 + 2) = pk2(fmaxf(lo,0.f), fmaxf(hi,0.f));
        upk(acc2[i][2], lo, hi);
        *(ull*)(sH + r*132 + c1)     = pk2(fmaxf(lo,0.f), fmaxf(hi,0.f));
        upk(acc2[i][3], lo, hi);
        *(ull*)(sH + r*132 + c1 + 2) = pk2(fmaxf(lo,0.f), fmaxf(hi,0.f));
    }
    for (int i = tid; i < CC*NCLS; i += 256)
        sW2[i] = W2[i];
    __syncthreads();

    // phase 2: hm = H @ W2 + b2, sigmoid, scatter (threads 0..127)
    if (tid < 128) {
        const int r   = tid & 63;
        const int grp = tid >> 6;      // 0 -> cls 0..4, 1 -> cls 5..9
        float o[5];
#pragma unroll
        for (int i = 0; i < 5; i++) o[i] = b2[grp*5 + i];
        for (int j = 0; j < 128; j++) {
            float a = sH[r*132 + j];
#pragma unroll
            for (int i = 0; i < 5; i++)
                o[i] = fmaf(a, sW2[j*NCLS + grp*5 + i], o[i]);
        }
        const int gr = rowBase + r;
        const int bi = idxs[gr*3], yi = idxs[gr*3+1], xi = idxs[gr*3+2];
        const int cell = yi*WG + xi;
#pragma unroll
        for (int i = 0; i < 5; i++) {
            int c = grp*5 + i;
            float heat = 1.f / (1.f + expf(-o[i]));
            g_heat[(bi*NCLS + c)*HW + cell] = heat;
        }
        if (grp == 0) g_map[bi*HW + cell] = gr;
    }
}

// ---------------- NMS + histogram -------------------------------------------
__global__ void nms_kernel() {
    int gid = blockIdx.x * blockDim.x + threadIdx.x;   // over B*HW
    if (gid >= BB*HW) return;
    if (g_map[gid] < 0) return;                        // empty cell: supp stays 0
    int b = gid / HW, cell = gid - b*HW;
    int y = cell / WG, x = cell - y*WG;
    bool inner = (y > 0) & (y < HH-1) & (x > 0) & (x < WG-1);
    const float* hb = g_heat + (size_t)b*NCLS*HW;
    for (int c = 0; c < NCLS; c++) {
        const float* hc = hb + c*HW;
        float ctr = hc[cell];
        float s;
        if (c >= 8) {
            s = ctr;
        } else if (!inner) {
            s = 0.f;   // border: local_max==0, heat>0 -> suppressed
        } else {
            bool keep = (ctr >= hc[cell-WG-1]) & (ctr >= hc[cell-WG]) & (ctr >= hc[cell-WG+1])
                      & (ctr >= hc[cell-1])                           & (ctr >= hc[cell+1])
                      & (ctr >= hc[cell+WG-1]) & (ctr >= hc[cell+WG]) & (ctr >= hc[cell+WG+1]);
            s = keep ? ctr : 0.f;
        }
        if (s > 0.f) {
            g_supp[((size_t)b*NCLS + c)*HW + cell] = s;
            atomicAdd(&g_hist[b*NBUCK + (__float_as_uint(s) >> 16)], 1u);
        }
    }
}

// ---------------- threshold bucket of rank-200 (warp-shuffle suffix scan) ---
__global__ void thresh_kernel() {
    __shared__ unsigned wtot[32], wexc[32];
    int b = blockIdx.x;
    const unsigned* h = g_hist + b*NBUCK;
    int t = threadIdx.x;                 // 1024 threads x 64 buckets
    const uint4* hv4 = (const uint4*)(h + t*64);
    unsigned v = 0;
#pragma unroll
    for (int i = 0; i < 16; i++) {
        uint4 u = hv4[i];
        v += u.x + u.y + u.z + u.w;
    }
    int lane = t & 31, wid = t >> 5;
    unsigned s = v;                      // inclusive lane-suffix within warp
#pragma unroll
    for (int off = 1; off < 32; off <<= 1) {
        unsigned u = __shfl_down_sync(0xFFFFFFFFu, s, off);
        if (lane + off < 32) s += u;
    }
    if (lane == 0) wtot[wid] = s;
    __syncthreads();
    if (wid == 0) {
        unsigned ws = wtot[lane];
        unsigned sw = ws;
#pragma unroll
        for (int off = 1; off < 32; off <<= 1) {
            unsigned u = __shfl_down_sync(0xFFFFFFFFu, sw, off);
            if (lane + off < 32) sw += u;
        }
        wexc[lane] = sw - ws;            // strict suffix of warp totals
    }
    __syncthreads();
    unsigned S = s + wexc[wid];          // suffix over all t' >= t
    unsigned Snext = S - v;
    if (S >= NPROP && Snext < NPROP) {   // exactly one thread
        unsigned acc = Snext;
        int T = t*64;
        for (int i = 63; i >= 0; i--) {
            unsigned c = h[t*64 + i];    // L1 hot
            if (acc + c >= NPROP) { T = t*64 + i; break; }
            acc += c;
        }
        g_thr[b] = T;
    }
}

// ---------------- gather candidates >= threshold from DENSE supp ------------
__global__ void gather_kernel() {
    const int N4 = BB*NCLS*HW/4;
    int gid = blockIdx.x * blockDim.x + threadIdx.x;
    if (gid >= N4) return;
    float4 v = ((const float4*)g_supp)[gid];
    int base = gid * 4;
    int b = base / (NCLS*HW);
    int T = g_thr[b];
    float vv[4] = {v.x, v.y, v.z, v.w};
#pragma unroll
    for (int u = 0; u < 4; u++) {
        unsigned vb = __float_as_uint(vv[u]);
        if ((int)(vb >> 16) >= T) {
            unsigned j = (unsigned)(base + u - b*NCLS*HW);   // key = c*HW + cell
            ull sk = ((ull)vb << 32) | (ull)(0xFFFFFFFFu - j);
            int p = atomicAdd(&g_selcnt[b], 1);
            if (p < SEL_CAP) g_sel[b*SEL_CAP + p] = sk;
        }
    }
}

// ---------------- exact rank of the small selected set ----------------------
__global__ void rank_kernel() {
    __shared__ ull sk[SEL_CAP];
    int b = blockIdx.x;
    int M = g_selcnt[b]; if (M > SEL_CAP) M = SEL_CAP;
    for (int i = threadIdx.x; i < M; i += blockDim.x) sk[i] = g_sel[b*SEL_CAP + i];
    __syncthreads();
    for (int i = threadIdx.x; i < M; i += blockDim.x) {
        ull v = sk[i];
        int r = 0;
        for (int j = 0; j < M; j++) r += (sk[j] > v);
        if (r < NPROP) g_top[b*NPROP + r] = v;
    }
}

// ---------------- assemble outputs ------------------------------------------
__global__ void out_kernel(const float* __restrict__ feat,
                           const float* __restrict__ Wcls,
                           const float* __restrict__ bcls,
                           float* __restrict__ out)
{
    int b = blockIdx.x / NPROP, p = blockIdx.x - b*NPROP;
    ull sk = g_top[b*NPROP + p];
    unsigned key = 0xFFFFFFFFu - (unsigned)(sk & 0xFFFFFFFFu);
    int cls = key / HW, idx = key - cls*HW;
    int c = threadIdx.x;
    int row = g_map[b*HW + idx];
    float f = (row >= 0) ? feat[(size_t)row*CC + c] : 0.f;
    out[OFF_QF + (b*CC + c)*NPROP + p] = f + Wcls[c*NCLS + cls] + bcls[c];
    if (c < NCLS)
        out[OFF_QHS + (b*NCLS + c)*NPROP + p] = g_supp[((size_t)b*NCLS + c)*HW + idx];
    if (c == 0) {
        out[OFF_POS + (b*NPROP + p)*2 + 0] = (float)(idx % WG);
        out[OFF_POS + (b*NPROP + p)*2 + 1] = (float)(idx / WG);
        out[OFF_CLS + b*NPROP + p] = (float)cls;
    }
}

// ---------------- launch ----------------------------------------------------
extern "C" void kernel_launch(void* const* d_in, const int* in_sizes, int n_in,
                              void* d_out, int out_size)
{
    const float* feat = (const float*)d_in[0];
    const float* W1   = (const float*)d_in[1];
    const float* b1   = (const float*)d_in[2];
    const float* W2   = (const float*)d_in[3];
    const float* b2   = (const float*)d_in[4];
    const float* Wcls = (const float*)d_in[5];
    const float* bcls = (const float*)d_in[6];
    const int*   idxs = (const int*)d_in[7];
    float* out = (float*)d_out;

    cudaFuncSetAttribute(gemm_kernel, cudaFuncAttributeMaxDynamicSharedMemorySize,
                         SMEM_FLOATS * (int)sizeof(float));

    // launch index 3 == gemm  (profiler captures index 3)
    initA_kernel<<<1024, 256>>>();
    initB_kernel<<<1024, 256>>>();
    initC_kernel<<<512, 256>>>();
    gemm_kernel<<<NPTS/64, 256, SMEM_FLOATS * sizeof(float)>>>(feat, W1, b1, W2, b2, idxs);
    nms_kernel<<<(BB*HW + 255)/256, 256>>>();
    thresh_kernel<<<BB, 1024>>>();
    gather_kernel<<<(BB*NCLS*HW/4 + 255)/256, 256>>>();
    rank_kernel<<<BB, 1024>>>();
    out_kernel<<<BB*NPROP, CC>>>(feat, Wcls, bcls, out);
}